// round 14
// baseline (speedup 1.0000x reference)
#include <cuda_runtime.h>
#include <cstdint>

typedef unsigned long long ull;

#define NCH 18
#define BPB 32          // boards per block (phase 1 = exactly one warp)
#define TPB 256         // threads per block

// ---------- bit helpers (bit index = i*8 + j, row-major) ----------
#define FILE_A 0x0101010101010101ULL
#define FILE_H 0x8080808080808080ULL
#define ALL64  0xFFFFFFFFFFFFFFFFULL
#define COLS_GE3 0xF8F8F8F8F8F8F8F8ULL

__device__ __forceinline__ ull Rs(ull x, int n) {
    const ull m = (0xFFULL >> n) * FILE_A;
    return (x >> n) & m;
}
__device__ __forceinline__ ull Ls(ull x, int n) {
    const ull m = ((0xFFULL << n) & 0xFFULL) * FILE_A;
    return (x << n) & m;
}

__device__ __forceinline__ ull tr8(ull x) {
    ull t;
    t = (x ^ (x >> 7))  & 0x00AA00AA00AA00AAULL; x = x ^ t ^ (t << 7);
    t = (x ^ (x >> 14)) & 0x0000CCCC0000CCCCULL; x = x ^ t ^ (t << 14);
    t = (x ^ (x >> 28)) & 0x00000000F0F0F0F0ULL; x = x ^ t ^ (t << 28);
    return x;
}

__device__ __forceinline__ void run_eq(ull m, int sh, ull fm, ull bm,
                                       ull& e1, ull& e2, ull& e3) {
    ull L1 = m;
    ull L2 = m & ((L1 << sh) & fm);
    ull L3 = m & ((L2 << sh) & fm);
    ull L4 = m & ((L3 << sh) & fm);
    ull R1 = m;
    ull R2 = m & ((R1 >> sh) & bm);
    ull R3 = m & ((R2 >> sh) & bm);
    ull R4 = m & ((R3 >> sh) & bm);
    ull ge2 = (L1 & R2) | (L2 & R1);
    ull ge3 = (L1 & R3) | (L2 & R2) | (L3 & R1);
    ull ge4 = (L1 & R4) | (L2 & R3) | (L3 & R2) | (L4 & R1);
    e1 |= m   & ~ge2;
    e2 |= ge2 & ~ge3;
    e3 |= ge3 & ~ge4;
}

__device__ __forceinline__ void conn3(ull m, ull& c1, ull& c2, ull& c3) {
    c1 = 0; c2 = 0; c3 = 0;
    run_eq(m, 1, ~FILE_A, ~FILE_H, c1, c2, c3);
    run_eq(m, 8, ALL64,   ALL64,   c1, c2, c3);
    run_eq(m, 9, ~FILE_A, ~FILE_H, c1, c2, c3);
    run_eq(m, 7, ~FILE_H, ~FILE_A, c1, c2, c3);
}

__device__ __forceinline__ void line_feats(ull me, ull op, ull empty,
                                           ull& live2, ull& live3, ull& rush3) {
    ull me1 = Rs(me, 1), me2 = Rs(me, 2), me3 = Rs(me, 3);
    ull notme = ~me;

    ull A  = me    & me1 & Rs(empty, 2) & Rs(empty, 3);
    ull Bm = empty & me1 & me2          & Rs(empty, 3);
    live2 = A | Ls(A, 1) | Ls(Bm, 1) | Ls(Bm, 2);

    ull core = me1 & me2 & me3;
    ull Cm = empty & core & Rs(empty, 4);
    live3 = Ls(Cm, 1) | Ls(Cm, 2) | Ls(Cm, 3);

    ull lb = Ls(op, 1) | FILE_A;
    ull rb = Rs(op, 5) | COLS_GE3;
    ull Dm = me & me1 & me2 & Rs(empty, 3) & Rs(notme, 4) & lb;
    ull open3 = notme & core & Rs(notme, 4);
    ull Em = open3 & (lb ^ rb);
    rush3 = Dm | Ls(Dm, 1) | Ls(Dm, 2) | Ls(Em, 1) | Ls(Em, 2) | Ls(Em, 3);
}

__device__ __forceinline__ void live_rush(ull me, ull op,
                                          ull& l2, ull& l3, ull& r3) {
    ull empty = ~(me | op);
    ull a, b, c;   line_feats(me, op, empty, a, b, c);
    ull a2, b2, c2;
    line_feats(tr8(me), tr8(op), tr8(empty), a2, b2, c2);
    l2 = a | tr8(a2);
    l3 = b | tr8(b2);
    r3 = c | tr8(c2);
}

// 256-bit streaming store (sm_100+ family, PTX ISA 8.8+)
__device__ __forceinline__ void st256_cs(float* p,
                                         float v0, float v1, float v2, float v3,
                                         float v4, float v5, float v6, float v7) {
    asm volatile("st.global.cs.v8.f32 [%0], {%1,%2,%3,%4,%5,%6,%7,%8};"
                 :: "l"(p), "f"(v0), "f"(v1), "f"(v2), "f"(v3),
                    "f"(v4), "f"(v5), "f"(v6), "f"(v7)
                 : "memory");
}

// ---------------- fused kernel ----------------
// Phase 1: warp 0 (threads 0..31) computes one board each -> smem masks.
// Phase 2: all 256 threads expand BPB*288 float4. Each thread handles one
// BYTE of a mask per iteration (8 cells = 32B contiguous) via one 256-bit
// streaming store: thread = (pair0 = t>>3, byte j = t&7); pair += TPB/8.
// Out byte addr = pair*256 + j*32 (warp covers 1024B contiguous).
__global__ void __launch_bounds__(TPB)
fused_kernel(const float* __restrict__ state,
             const float* __restrict__ side,
             float* __restrict__ out, int nb) {
    __shared__ ull masks[BPB * NCH];   // 4608 B

    int t  = threadIdx.x;
    int b0 = blockIdx.x * BPB;
    int b  = b0 + t;

    if (t < BPB && b < nb) {
        float s  = side[b];
        float ns = -s;
        const float4* sp = reinterpret_cast<const float4*>(state) + (size_t)b * 16;

        ull my = 0, op = 0;
#pragma unroll
        for (int q = 0; q < 16; q++) {
            float4 v = sp[q];
            int base = q * 4;
            my |= ((ull)(v.x == s)  << base)       | ((ull)(v.y == s)  << (base + 1))
                | ((ull)(v.z == s)  << (base + 2)) | ((ull)(v.w == s)  << (base + 3));
            op |= ((ull)(v.x == ns) << base)       | ((ull)(v.y == ns) << (base + 1))
                | ((ull)(v.z == ns) << (base + 2)) | ((ull)(v.w == ns) << (base + 3));
        }

        ull* dst = &masks[t * NCH];
        dst[0] = my;
        dst[1] = op;
        {
            ull c1, c2, c3;
            conn3(my, c1, c2, c3);
            dst[2] = c1; dst[3] = c2; dst[4] = c3;
            conn3(op, c1, c2, c3);
            dst[5] = c1; dst[6] = c2; dst[7] = c3;
        }
        {
            ull l2m, l3m, r3m;
            live_rush(my, op, l2m, l3m, r3m);
            dst[8]  = l2m; dst[9]  = l3m; dst[10] = r3m;
            dst[11] = (__popcll(l2m) >= 2) ? ALL64 : 0ULL;
            dst[12] = ((__popcll(l3m) + __popcll(r3m)) >= 2) ? ALL64 : 0ULL;
        }
        {
            ull l2o, l3o, r3o;
            live_rush(op, my, l2o, l3o, r3o);
            dst[13] = l2o; dst[14] = l3o; dst[15] = r3o;
            dst[16] = (__popcll(l2o) >= 2) ? ALL64 : 0ULL;
            dst[17] = ((__popcll(l3o) + __popcll(r3o)) >= 2) ? ALL64 : 0ULL;
        }
    }
    __syncthreads();

    int nBoards = nb - b0;
    if (nBoards > BPB) nBoards = BPB;
    if (nBoards <= 0) return;
    int npairs = nBoards * NCH;        // (board, channel) pairs; 64 floats each

    int j    = t & 7;                  // byte index within 64-bit mask
    int pair = t >> 3;                 // starts 0..31, stride 32
    unsigned sh = (j & 3) * 8;
    int wsel = j >> 2;

    const unsigned* mw = reinterpret_cast<const unsigned*>(masks) + wsel;
    float* dst = out + (size_t)b0 * 1152 + j * 8;   // 1152 floats per board
    const float ONE = 1.0f;

#pragma unroll 6
    for (; pair < npairs; pair += TPB / 8) {
        unsigned w = mw[pair * 2];
        unsigned bits = w >> sh;
        st256_cs(dst + pair * 64,
                 (bits & 1u)   ? ONE : 0.0f,
                 (bits & 2u)   ? ONE : 0.0f,
                 (bits & 4u)   ? ONE : 0.0f,
                 (bits & 8u)   ? ONE : 0.0f,
                 (bits & 16u)  ? ONE : 0.0f,
                 (bits & 32u)  ? ONE : 0.0f,
                 (bits & 64u)  ? ONE : 0.0f,
                 (bits & 128u) ? ONE : 0.0f);
    }
}

extern "C" void kernel_launch(void* const* d_in, const int* in_sizes, int n_in,
                              void* d_out, int out_size) {
    const float* state = (const float*)d_in[0];
    const float* side  = (const float*)d_in[1];
    int nb = in_sizes[0] / 64;

    int blocks = (nb + BPB - 1) / BPB;
    fused_kernel<<<blocks, TPB>>>(state, side, (float*)d_out, nb);
}

// round 15
// speedup vs baseline: 1.1121x; 1.1121x over previous
#include <cuda_runtime.h>
#include <cstdint>

typedef unsigned long long ull;

#define NCH 18
#define BPB 32          // boards per block (phase 1 = exactly one warp)
#define TPB 256         // threads per block

// ---------- bit helpers (bit index = i*8 + j, row-major) ----------
#define FILE_A 0x0101010101010101ULL
#define FILE_H 0x8080808080808080ULL
#define ALL64  0xFFFFFFFFFFFFFFFFULL
#define COLS_GE3 0xF8F8F8F8F8F8F8F8ULL

__device__ __forceinline__ ull Rs(ull x, int n) {
    const ull m = (0xFFULL >> n) * FILE_A;
    return (x >> n) & m;
}
__device__ __forceinline__ ull Ls(ull x, int n) {
    const ull m = ((0xFFULL << n) & 0xFFULL) * FILE_A;
    return (x << n) & m;
}

__device__ __forceinline__ ull tr8(ull x) {
    ull t;
    t = (x ^ (x >> 7))  & 0x00AA00AA00AA00AAULL; x = x ^ t ^ (t << 7);
    t = (x ^ (x >> 14)) & 0x0000CCCC0000CCCCULL; x = x ^ t ^ (t << 14);
    t = (x ^ (x >> 28)) & 0x00000000F0F0F0F0ULL; x = x ^ t ^ (t << 28);
    return x;
}

__device__ __forceinline__ void run_eq(ull m, int sh, ull fm, ull bm,
                                       ull& e1, ull& e2, ull& e3) {
    ull L1 = m;
    ull L2 = m & ((L1 << sh) & fm);
    ull L3 = m & ((L2 << sh) & fm);
    ull L4 = m & ((L3 << sh) & fm);
    ull R1 = m;
    ull R2 = m & ((R1 >> sh) & bm);
    ull R3 = m & ((R2 >> sh) & bm);
    ull R4 = m & ((R3 >> sh) & bm);
    ull ge2 = (L1 & R2) | (L2 & R1);
    ull ge3 = (L1 & R3) | (L2 & R2) | (L3 & R1);
    ull ge4 = (L1 & R4) | (L2 & R3) | (L3 & R2) | (L4 & R1);
    e1 |= m   & ~ge2;
    e2 |= ge2 & ~ge3;
    e3 |= ge3 & ~ge4;
}

__device__ __forceinline__ void conn3(ull m, ull& c1, ull& c2, ull& c3) {
    c1 = 0; c2 = 0; c3 = 0;
    run_eq(m, 1, ~FILE_A, ~FILE_H, c1, c2, c3);
    run_eq(m, 8, ALL64,   ALL64,   c1, c2, c3);
    run_eq(m, 9, ~FILE_A, ~FILE_H, c1, c2, c3);
    run_eq(m, 7, ~FILE_H, ~FILE_A, c1, c2, c3);
}

__device__ __forceinline__ void line_feats(ull me, ull op, ull empty,
                                           ull& live2, ull& live3, ull& rush3) {
    ull me1 = Rs(me, 1), me2 = Rs(me, 2), me3 = Rs(me, 3);
    ull notme = ~me;

    ull A  = me    & me1 & Rs(empty, 2) & Rs(empty, 3);
    ull Bm = empty & me1 & me2          & Rs(empty, 3);
    live2 = A | Ls(A, 1) | Ls(Bm, 1) | Ls(Bm, 2);

    ull core = me1 & me2 & me3;
    ull Cm = empty & core & Rs(empty, 4);
    live3 = Ls(Cm, 1) | Ls(Cm, 2) | Ls(Cm, 3);

    ull lb = Ls(op, 1) | FILE_A;
    ull rb = Rs(op, 5) | COLS_GE3;
    ull Dm = me & me1 & me2 & Rs(empty, 3) & Rs(notme, 4) & lb;
    ull open3 = notme & core & Rs(notme, 4);
    ull Em = open3 & (lb ^ rb);
    rush3 = Dm | Ls(Dm, 1) | Ls(Dm, 2) | Ls(Em, 1) | Ls(Em, 2) | Ls(Em, 3);
}

__device__ __forceinline__ void live_rush(ull me, ull op,
                                          ull& l2, ull& l3, ull& r3) {
    ull empty = ~(me | op);
    ull a, b, c;   line_feats(me, op, empty, a, b, c);
    ull a2, b2, c2;
    line_feats(tr8(me), tr8(op), tr8(empty), a2, b2, c2);
    l2 = a | tr8(a2);
    l3 = b | tr8(b2);
    r3 = c | tr8(c2);
}

// ---------------- fused kernel ----------------
// Phase 1: warp 0 (threads 0..31) computes one board each -> smem masks.
// Phase 2: all 256 threads expand BPB*288 float4 with zero index decode:
//   thread = (pair0 = t>>4, nib = t&15); pair walks += TPB/16.
// Stores use __stcs (evict-first): best measured steady-state bench; output
// stream (151MB) exceeds L2, early drain + no read-residency thrash.
__global__ void __launch_bounds__(TPB)
fused_kernel(const float* __restrict__ state,
             const float* __restrict__ side,
             float4* __restrict__ out, int nb) {
    __shared__ ull masks[BPB * NCH];   // 4608 B

    int t  = threadIdx.x;
    int b0 = blockIdx.x * BPB;
    int b  = b0 + t;

    if (t < BPB && b < nb) {
        float s  = side[b];
        float ns = -s;
        const float4* sp = reinterpret_cast<const float4*>(state) + (size_t)b * 16;

        ull my = 0, op = 0;
#pragma unroll
        for (int q = 0; q < 16; q++) {
            float4 v = sp[q];
            int base = q * 4;
            my |= ((ull)(v.x == s)  << base)       | ((ull)(v.y == s)  << (base + 1))
                | ((ull)(v.z == s)  << (base + 2)) | ((ull)(v.w == s)  << (base + 3));
            op |= ((ull)(v.x == ns) << base)       | ((ull)(v.y == ns) << (base + 1))
                | ((ull)(v.z == ns) << (base + 2)) | ((ull)(v.w == ns) << (base + 3));
        }

        ull* dst = &masks[t * NCH];
        dst[0] = my;
        dst[1] = op;
        {
            ull c1, c2, c3;
            conn3(my, c1, c2, c3);
            dst[2] = c1; dst[3] = c2; dst[4] = c3;
            conn3(op, c1, c2, c3);
            dst[5] = c1; dst[6] = c2; dst[7] = c3;
        }
        {
            ull l2m, l3m, r3m;
            live_rush(my, op, l2m, l3m, r3m);
            dst[8]  = l2m; dst[9]  = l3m; dst[10] = r3m;
            dst[11] = (__popcll(l2m) >= 2) ? ALL64 : 0ULL;
            dst[12] = ((__popcll(l3m) + __popcll(r3m)) >= 2) ? ALL64 : 0ULL;
        }
        {
            ull l2o, l3o, r3o;
            live_rush(op, my, l2o, l3o, r3o);
            dst[13] = l2o; dst[14] = l3o; dst[15] = r3o;
            dst[16] = (__popcll(l2o) >= 2) ? ALL64 : 0ULL;
            dst[17] = ((__popcll(l3o) + __popcll(r3o)) >= 2) ? ALL64 : 0ULL;
        }
    }
    __syncthreads();

    int nBoards = nb - b0;
    if (nBoards > BPB) nBoards = BPB;
    if (nBoards <= 0) return;
    int npairs = nBoards * NCH;

    int nib  = t & 15;
    int pair = t >> 4;
    unsigned sh = (nib & 7) * 4;
    int wsel = nib >> 3;

    const unsigned* mw  = reinterpret_cast<const unsigned*>(masks) + wsel;
    float4* dst = out + (size_t)b0 * 288 + nib;
    const unsigned one = 0x3F800000u;   // 1.0f bits

#pragma unroll 8
    for (; pair < npairs; pair += TPB / 16) {
        unsigned w = mw[pair * 2];
        unsigned bits = w >> sh;
        float4 v;
        v.x = __uint_as_float((bits & 1u) ? one : 0u);
        v.y = __uint_as_float((bits & 2u) ? one : 0u);
        v.z = __uint_as_float((bits & 4u) ? one : 0u);
        v.w = __uint_as_float((bits & 8u) ? one : 0u);
        __stcs(&dst[pair * 16], v);      // evict-first streaming store
    }
}

extern "C" void kernel_launch(void* const* d_in, const int* in_sizes, int n_in,
                              void* d_out, int out_size) {
    const float* state = (const float*)d_in[0];
    const float* side  = (const float*)d_in[1];
    int nb = in_sizes[0] / 64;

    int blocks = (nb + BPB - 1) / BPB;
    fused_kernel<<<blocks, TPB>>>(state, side, (float4*)d_out, nb);
}

// round 16
// speedup vs baseline: 1.1218x; 1.0088x over previous
#include <cuda_runtime.h>
#include <cstdint>

typedef unsigned long long ull;

#define NCH 18
#define BPB 16          // boards per block (finer granularity, grid = 2048)
#define TPB 256         // threads per block

// ---------- bit helpers (bit index = i*8 + j, row-major) ----------
#define FILE_A 0x0101010101010101ULL
#define FILE_H 0x8080808080808080ULL
#define ALL64  0xFFFFFFFFFFFFFFFFULL
#define COLS_GE3 0xF8F8F8F8F8F8F8F8ULL

__device__ __forceinline__ ull Rs(ull x, int n) {
    const ull m = (0xFFULL >> n) * FILE_A;
    return (x >> n) & m;
}
__device__ __forceinline__ ull Ls(ull x, int n) {
    const ull m = ((0xFFULL << n) & 0xFFULL) * FILE_A;
    return (x << n) & m;
}

__device__ __forceinline__ ull tr8(ull x) {
    ull t;
    t = (x ^ (x >> 7))  & 0x00AA00AA00AA00AAULL; x = x ^ t ^ (t << 7);
    t = (x ^ (x >> 14)) & 0x0000CCCC0000CCCCULL; x = x ^ t ^ (t << 14);
    t = (x ^ (x >> 28)) & 0x00000000F0F0F0F0ULL; x = x ^ t ^ (t << 28);
    return x;
}

__device__ __forceinline__ void run_eq(ull m, int sh, ull fm, ull bm,
                                       ull& e1, ull& e2, ull& e3) {
    ull L1 = m;
    ull L2 = m & ((L1 << sh) & fm);
    ull L3 = m & ((L2 << sh) & fm);
    ull L4 = m & ((L3 << sh) & fm);
    ull R1 = m;
    ull R2 = m & ((R1 >> sh) & bm);
    ull R3 = m & ((R2 >> sh) & bm);
    ull R4 = m & ((R3 >> sh) & bm);
    ull ge2 = (L1 & R2) | (L2 & R1);
    ull ge3 = (L1 & R3) | (L2 & R2) | (L3 & R1);
    ull ge4 = (L1 & R4) | (L2 & R3) | (L3 & R2) | (L4 & R1);
    e1 |= m   & ~ge2;
    e2 |= ge2 & ~ge3;
    e3 |= ge3 & ~ge4;
}

__device__ __forceinline__ void conn3(ull m, ull& c1, ull& c2, ull& c3) {
    c1 = 0; c2 = 0; c3 = 0;
    run_eq(m, 1, ~FILE_A, ~FILE_H, c1, c2, c3);
    run_eq(m, 8, ALL64,   ALL64,   c1, c2, c3);
    run_eq(m, 9, ~FILE_A, ~FILE_H, c1, c2, c3);
    run_eq(m, 7, ~FILE_H, ~FILE_A, c1, c2, c3);
}

__device__ __forceinline__ void line_feats(ull me, ull op, ull empty,
                                           ull& live2, ull& live3, ull& rush3) {
    ull me1 = Rs(me, 1), me2 = Rs(me, 2), me3 = Rs(me, 3);
    ull notme = ~me;

    ull A  = me    & me1 & Rs(empty, 2) & Rs(empty, 3);
    ull Bm = empty & me1 & me2          & Rs(empty, 3);
    live2 = A | Ls(A, 1) | Ls(Bm, 1) | Ls(Bm, 2);

    ull core = me1 & me2 & me3;
    ull Cm = empty & core & Rs(empty, 4);
    live3 = Ls(Cm, 1) | Ls(Cm, 2) | Ls(Cm, 3);

    ull lb = Ls(op, 1) | FILE_A;
    ull rb = Rs(op, 5) | COLS_GE3;
    ull Dm = me & me1 & me2 & Rs(empty, 3) & Rs(notme, 4) & lb;
    ull open3 = notme & core & Rs(notme, 4);
    ull Em = open3 & (lb ^ rb);
    rush3 = Dm | Ls(Dm, 1) | Ls(Dm, 2) | Ls(Em, 1) | Ls(Em, 2) | Ls(Em, 3);
}

__device__ __forceinline__ void live_rush(ull me, ull op,
                                          ull& l2, ull& l3, ull& r3) {
    ull empty = ~(me | op);
    ull a, b, c;   line_feats(me, op, empty, a, b, c);
    ull a2, b2, c2;
    line_feats(tr8(me), tr8(op), tr8(empty), a2, b2, c2);
    l2 = a | tr8(a2);
    l3 = b | tr8(b2);
    r3 = c | tr8(c2);
}

// ---------------- fused kernel ----------------
// Phase 1: threads 0..BPB-1 compute one board each -> smem masks.
// Phase 2: all 256 threads expand BPB*288 float4 with zero index decode:
//   thread = (pair0 = t>>4, nib = t&15); pair walks += TPB/16.
// Stores use __stcs (evict-first): best measured steady-state bench.
// Grid = 2048 blocks: sub-1% wave tail, 2x block turnover -> phase-1 bubbles
// of incoming blocks hide under co-resident blocks' store streams.
__global__ void __launch_bounds__(TPB)
fused_kernel(const float* __restrict__ state,
             const float* __restrict__ side,
             float4* __restrict__ out, int nb) {
    __shared__ ull masks[BPB * NCH];   // 2304 B

    int t  = threadIdx.x;
    int b0 = blockIdx.x * BPB;
    int b  = b0 + t;

    if (t < BPB && b < nb) {
        float s  = side[b];
        float ns = -s;
        const float4* sp = reinterpret_cast<const float4*>(state) + (size_t)b * 16;

        ull my = 0, op = 0;
#pragma unroll
        for (int q = 0; q < 16; q++) {
            float4 v = sp[q];
            int base = q * 4;
            my |= ((ull)(v.x == s)  << base)       | ((ull)(v.y == s)  << (base + 1))
                | ((ull)(v.z == s)  << (base + 2)) | ((ull)(v.w == s)  << (base + 3));
            op |= ((ull)(v.x == ns) << base)       | ((ull)(v.y == ns) << (base + 1))
                | ((ull)(v.z == ns) << (base + 2)) | ((ull)(v.w == ns) << (base + 3));
        }

        ull* dst = &masks[t * NCH];
        dst[0] = my;
        dst[1] = op;
        {
            ull c1, c2, c3;
            conn3(my, c1, c2, c3);
            dst[2] = c1; dst[3] = c2; dst[4] = c3;
            conn3(op, c1, c2, c3);
            dst[5] = c1; dst[6] = c2; dst[7] = c3;
        }
        {
            ull l2m, l3m, r3m;
            live_rush(my, op, l2m, l3m, r3m);
            dst[8]  = l2m; dst[9]  = l3m; dst[10] = r3m;
            dst[11] = (__popcll(l2m) >= 2) ? ALL64 : 0ULL;
            dst[12] = ((__popcll(l3m) + __popcll(r3m)) >= 2) ? ALL64 : 0ULL;
        }
        {
            ull l2o, l3o, r3o;
            live_rush(op, my, l2o, l3o, r3o);
            dst[13] = l2o; dst[14] = l3o; dst[15] = r3o;
            dst[16] = (__popcll(l2o) >= 2) ? ALL64 : 0ULL;
            dst[17] = ((__popcll(l3o) + __popcll(r3o)) >= 2) ? ALL64 : 0ULL;
        }
    }
    __syncthreads();

    int nBoards = nb - b0;
    if (nBoards > BPB) nBoards = BPB;
    if (nBoards <= 0) return;
    int npairs = nBoards * NCH;

    int nib  = t & 15;
    int pair = t >> 4;
    unsigned sh = (nib & 7) * 4;
    int wsel = nib >> 3;

    const unsigned* mw  = reinterpret_cast<const unsigned*>(masks) + wsel;
    float4* dst = out + (size_t)b0 * 288 + nib;
    const unsigned one = 0x3F800000u;   // 1.0f bits

#pragma unroll 6
    for (; pair < npairs; pair += TPB / 16) {
        unsigned w = mw[pair * 2];
        unsigned bits = w >> sh;
        float4 v;
        v.x = __uint_as_float((bits & 1u) ? one : 0u);
        v.y = __uint_as_float((bits & 2u) ? one : 0u);
        v.z = __uint_as_float((bits & 4u) ? one : 0u);
        v.w = __uint_as_float((bits & 8u) ? one : 0u);
        __stcs(&dst[pair * 16], v);      // evict-first streaming store
    }
}

extern "C" void kernel_launch(void* const* d_in, const int* in_sizes, int n_in,
                              void* d_out, int out_size) {
    const float* state = (const float*)d_in[0];
    const float* side  = (const float*)d_in[1];
    int nb = in_sizes[0] / 64;

    int blocks = (nb + BPB - 1) / BPB;
    fused_kernel<<<blocks, TPB>>>(state, side, (float4*)d_out, nb);
}